// round 13
// baseline (speedup 1.0000x reference)
#include <cuda_runtime.h>
#include <cuda_fp16.h>
#include <math_constants.h>
#include <cstdint>

// =============================================================================
// VQ forward, hybrid tensor+FMA pipe split (compute_103-safe PTX):
//   score(n,j) = ||c_j||^2 - 2*fp16(x_n).fp16(c_j), additive over k:
//     dims 0..239  -> mma.sync fp16/f32-acc (tensor pipe, critical path)
//     dims 240..255-> FFMA from the same smem tiles (fills idle fma pipe)
//   split-K(codebook): 1024 CTAs emit packed top-2 cands; vq_select merges,
//   exact-fp32 rescores within margin, gathers + MSE; last block writes loss.
// =============================================================================

#define DDIM 256
#define TILE_M 128          // tokens per CTA
#define TILE_N 128          // codes per n-chunk
#define NPART 4             // codebook split factor
#define KSLICE 2048         // codes per CTA
#define MAX_N 65536
#define MAX_K 8192
#define SEL_BLOCKS 4096
#define MARGIN 0.3f

#define B_OFF     65536     // A tile: 128 rows x 512B = 64KB
#define B_STAGE   16384     // 128 codes x 64 halves x 2B
#define SMEM_TOTAL (B_OFF + 2 * B_STAGE)    // 98304 B -> 2 CTAs/SM

__device__ float    g_cnorm[MAX_K];
__device__ float    g_partial[SEL_BLOCKS];
__device__ int      g_done;
__device__ __half   g_cb_h[MAX_K * DDIM];
__device__ uint32_t g_cand[MAX_N * 128];    // 32 packed cands x NPART per token

// ------------------------------------------------------------------ helpers
__device__ __forceinline__ uint32_t smem_u32(const void* p) {
    uint32_t a;
    asm("{ .reg .u64 t; cvta.to.shared.u64 t, %1; cvt.u32.u64 %0, t; }"
        : "=r"(a) : "l"(p));
    return a;
}
__device__ __forceinline__ void cp_async16(uint32_t dst, const void* src) {
    asm volatile("cp.async.cg.shared.global [%0], [%1], 16;"
                 :: "r"(dst), "l"(src) : "memory");
}
#define CP_COMMIT() asm volatile("cp.async.commit_group;" ::: "memory")
#define CP_WAIT1()  asm volatile("cp.async.wait_group 1;" ::: "memory")
#define CP_WAIT0()  asm volatile("cp.async.wait_group 0;" ::: "memory")

__device__ __forceinline__ void ldsm4(uint32_t& r0, uint32_t& r1, uint32_t& r2,
                                      uint32_t& r3, uint32_t addr) {
    asm volatile("ldmatrix.sync.aligned.m8n8.x4.shared.b16 {%0,%1,%2,%3}, [%4];"
                 : "=r"(r0), "=r"(r1), "=r"(r2), "=r"(r3) : "r"(addr));
}
__device__ __forceinline__ void mma16816(float* d, const uint32_t* a,
                                         uint32_t b0, uint32_t b1) {
    asm volatile(
        "mma.sync.aligned.m16n8k16.row.col.f32.f16.f16.f32 "
        "{%0,%1,%2,%3}, {%4,%5,%6,%7}, {%8,%9}, {%0,%1,%2,%3};"
        : "+f"(d[0]), "+f"(d[1]), "+f"(d[2]), "+f"(d[3])
        : "r"(a[0]), "r"(a[1]), "r"(a[2]), "r"(a[3]), "r"(b0), "r"(b1));
}
__device__ __forceinline__ uint32_t pack2(unsigned short a, unsigned short b) {
    return (uint32_t)a | ((uint32_t)b << 16);
}
// monotone float<->uint order flip
__device__ __forceinline__ uint32_t fflip(float s) {
    uint32_t u = __float_as_uint(s);
    return u ^ ((uint32_t)((int32_t)u >> 31) | 0x80000000u);
}
__device__ __forceinline__ float funflip(uint32_t u) {
    uint32_t m = (u & 0x80000000u) ? 0x80000000u : 0xFFFFFFFFu;
    return __uint_as_float(u ^ m);
}

// ---------------------------------------------------------------------------
// Kernel 1: fused codebook norms + fp32->fp16 convert. One warp per code row.
//           Block 0 also resets the done counter (graph-replay safe).
// ---------------------------------------------------------------------------
__global__ __launch_bounds__(256)
void vq_prep(const float* __restrict__ cb, int K) {
    if (blockIdx.x == 0 && threadIdx.x == 0) g_done = 0;
    int row = blockIdx.x * 8 + (threadIdx.x >> 5);
    int lane = threadIdx.x & 31;
    if (row >= K) return;
    const float4* src = reinterpret_cast<const float4*>(cb + (size_t)row * DDIM);
    float4 v0 = src[lane * 2], v1 = src[lane * 2 + 1];
    float f[8] = {v0.x, v0.y, v0.z, v0.w, v1.x, v1.y, v1.z, v1.w};
    float s = 0.f;
    unsigned short h[8];
#pragma unroll
    for (int c = 0; c < 8; c++) {
        s += f[c] * f[c];
        h[c] = __half_as_ushort(__float2half_rn(f[c]));
    }
#pragma unroll
    for (int o = 16; o > 0; o >>= 1) s += __shfl_down_sync(0xFFFFFFFFu, s, o);
    if (lane == 0) g_cnorm[row] = s;
    reinterpret_cast<uint4*>(g_cb_h + (size_t)row * DDIM)[lane] =
        make_uint4(pack2(h[0], h[1]), pack2(h[2], h[3]),
                   pack2(h[4], h[5]), pack2(h[6], h[7]));
}

// ---------------------------------------------------------------------------
// Kernel 2: hybrid GEMM (128 tokens x 2048 codes) + per-thread top-2 ->
//           packed candidates to global. blockIdx: tile = bx>>2, part = bx&3.
// ---------------------------------------------------------------------------
__global__ __launch_bounds__(256, 2)
void vq_gemm(const float* __restrict__ x) {
    extern __shared__ __align__(1024) char smem[];
    const uint32_t sb = smem_u32(smem);
    const int tid = threadIdx.x;
    const int lane = tid & 31;
    const int warp = tid >> 5;
    const int warp_m = warp >> 2;          // 0..1
    const int warp_n = warp & 3;           // 0..3
    const int part = blockIdx.x & 3;
    const int m0 = (blockIdx.x >> 2) * TILE_M;
    const int n_part0 = part * KSLICE;
    const int G = (KSLICE / TILE_N) * 4;   // 64 B-slices

    // ---- A: load x rows, convert to fp16, swizzled smem (64KB) ----
    for (int g = tid; g < TILE_M * 32; g += 256) {       // 16B granules
        int r = g >> 5, gk = g & 31;
        const float4* src =
            reinterpret_cast<const float4*>(x + (size_t)(m0 + r) * DDIM + gk * 8);
        float4 v0 = src[0], v1 = src[1];
        float f[8] = {v0.x, v0.y, v0.z, v0.w, v1.x, v1.y, v1.z, v1.w};
        unsigned short hs[8];
#pragma unroll
        for (int c = 0; c < 8; c++) hs[c] = __half_as_ushort(__float2half_rn(f[c]));
        uint32_t off = r * 512 + (gk >> 3) * 128 + ((((gk ^ r) & 7)) << 4);
        *reinterpret_cast<uint4*>(smem + off) =
            make_uint4(pack2(hs[0], hs[1]), pack2(hs[2], hs[3]),
                       pack2(hs[4], hs[5]), pack2(hs[6], hs[7]));
    }

    // ---- per-lane ldmatrix address bases ----
    const int a_row = warp_m * 64 + (lane & 15);
    const int a_r7 = a_row & 7;
    uint32_t a_base[4];
#pragma unroll
    for (int mf = 0; mf < 4; mf++) a_base[mf] = sb + (a_row + mf * 16) * 512;
    const int b_nlo = (lane & 7) + ((lane >> 4) << 3);
    const int b_gbit = (lane >> 3) & 1;
    uint32_t b_rowoff[2];
#pragma unroll
    for (int p = 0; p < 2; p++)
        b_rowoff[p] = (warp_n * 32 + p * 16 + b_nlo) * 128;

    float acc[4][4][4];
#pragma unroll
    for (int a1 = 0; a1 < 4; a1++)
#pragma unroll
        for (int a2 = 0; a2 < 4; a2++)
#pragma unroll
            for (int a3 = 0; a3 < 4; a3++) acc[a1][a2][a3] = 0.f;

    float tv0[8], tv1[8];
    int   ti0[8], ti1[8];
#pragma unroll
    for (int s = 0; s < 8; s++) {
        tv0[s] = tv1[s] = CUDART_INF_F;
        ti0[s] = ti1[s] = 0;
    }

    // ---- B slice producer (all 256 threads, 4 x 16B each) ----
    auto issueB = [&](int g) {
        int nc = g >> 2, kc = g & 3;
        const __half* gb =
            g_cb_h + (size_t)(n_part0 + nc * TILE_N) * DDIM + kc * 64;
        uint32_t bbuf = sb + B_OFF + (g & 1) * B_STAGE;
#pragma unroll
        for (int j = 0; j < 4; j++) {
            int lin = tid + j * 256;
            int n = lin >> 3, gk = lin & 7;
            cp_async16(bbuf + n * 128 + (((gk ^ n) & 7) << 4),
                       gb + (size_t)n * DDIM + gk * 8);
        }
        CP_COMMIT();
    };

    issueB(0);

    for (int g = 0; g < G; g++) {
        __syncthreads();                     // prior reads of buf[(g+1)&1] done
        if (g + 1 < G) { issueB(g + 1); CP_WAIT1(); }
        else           { CP_WAIT0(); }
        __syncthreads();                     // slice g visible to all

        const uint32_t bbuf = sb + B_OFF + (g & 1) * B_STAGE;
        const int kc = g & 3;
        const int smax = (kc == 3) ? 3 : 4;  // tensor skips dims 240..255
        for (int s = 0; s < smax; s++) {     // k16 steps within slice
            uint32_t br[8];
#pragma unroll
            for (int p = 0; p < 2; p++) {
                int gk = s * 2 + b_gbit;
                uint32_t addr = bbuf + b_rowoff[p] + (((gk ^ b_nlo) & 7) << 4);
                ldsm4(br[p * 4 + 0], br[p * 4 + 1], br[p * 4 + 2], br[p * 4 + 3], addr);
            }
            int kabs = kc * 4 + s;
            int ga = kabs * 2 + (lane >> 4);
            uint32_t aoff = (ga >> 3) * 128 + ((((ga & 7) ^ a_r7)) << 4);
#pragma unroll
            for (int mf = 0; mf < 4; mf++) {
                uint32_t ar[4];
                ldsm4(ar[0], ar[1], ar[2], ar[3], a_base[mf] + aoff);
#pragma unroll
                for (int nf = 0; nf < 4; nf++)
                    mma16816(acc[mf][nf], ar, br[(nf >> 1) * 4 + (nf & 1) * 2],
                             br[(nf >> 1) * 4 + (nf & 1) * 2 + 1]);
            }
        }

        if (kc == 3) {
            // ---- FFMA path: dims 240..255 from the same smem tiles, into
            //      the same f32 accumulators (fills the idle fma pipe) ----
            const int r4 = lane >> 2;
            const int c2 = (lane & 3) * 2;
#pragma unroll
            for (int kp = 0; kp < 8; kp++) {         // 8 k-pairs = 16 dims
                const int hi = kp >> 2;              // granule half
                const int byo = (kp & 3) * 4;
                float2 av[8];
#pragma unroll
                for (int slot = 0; slot < 8; slot++) {
                    int row = warp_m * 64 + (slot >> 1) * 16 + (slot & 1) * 8 + r4;
                    uint32_t ao = row * 512 + 384 +
                                  ((((30 + hi) ^ row) & 7) << 4) + byo;
                    av[slot] = __half22float2(
                        *reinterpret_cast<const __half2*>(smem + ao));
                }
#pragma unroll
                for (int nf = 0; nf < 4; nf++) {
#pragma unroll
                    for (int q = 0; q < 2; q++) {
                        int col = warp_n * 32 + nf * 8 + c2 + q;
                        uint32_t bo = B_OFF + (g & 1) * B_STAGE + col * 128 +
                                      ((((6 + hi) ^ col) & 7) << 4) + byo;
                        float2 bv = __half22float2(
                            *reinterpret_cast<const __half2*>(smem + bo));
#pragma unroll
                        for (int mf = 0; mf < 4; mf++) {
#pragma unroll
                            for (int h = 0; h < 2; h++) {
                                acc[mf][nf][h * 2 + q] =
                                    fmaf(av[mf * 2 + h].x, bv.x,
                                    fmaf(av[mf * 2 + h].y, bv.y,
                                         acc[mf][nf][h * 2 + q]));
                            }
                        }
                    }
                }
            }

            // ---- fold chunk scores into per-row top-2 ----
            int n_base = n_part0 + (g >> 2) * TILE_N + warp_n * 32 + c2;
#pragma unroll
            for (int nf = 0; nf < 4; nf++) {
                int ncol = n_base + nf * 8;
                float cn0 = __ldg(&g_cnorm[ncol]);
                float cn1 = __ldg(&g_cnorm[ncol + 1]);
#pragma unroll
                for (int mf = 0; mf < 4; mf++) {
#pragma unroll
                    for (int h = 0; h < 2; h++) {
                        int slot = mf * 2 + h;
                        float s0 = fmaf(-2.f, acc[mf][nf][h * 2 + 0], cn0);
                        float s1 = fmaf(-2.f, acc[mf][nf][h * 2 + 1], cn1);
#pragma unroll
                        for (int q = 0; q < 2; q++) {
                            float sv = q ? s1 : s0;
                            int   si = ncol + q;
                            if (sv < tv1[slot]) {
                                if (sv < tv0[slot]) {
                                    tv1[slot] = tv0[slot]; ti1[slot] = ti0[slot];
                                    tv0[slot] = sv;        ti0[slot] = si;
                                } else { tv1[slot] = sv; ti1[slot] = si; }
                            }
                        }
                        acc[mf][nf][h * 2 + 0] = 0.f;
                        acc[mf][nf][h * 2 + 1] = 0.f;
                    }
                }
            }
        }
    }

    // ---- write packed candidates straight to global (no tail compute) ----
    const int t16 = warp_n * 4 + (lane & 3);
#pragma unroll
    for (int slot = 0; slot < 8; slot++) {
        int row = warp_m * 64 + (slot >> 1) * 16 + (lane >> 2) + (slot & 1) * 8;
        size_t base = (size_t)(m0 + row) * 128 + part * 32 + t16 * 2;
        g_cand[base + 0] = (fflip(tv0[slot]) & 0xFFFFE000u) | (uint32_t)ti0[slot];
        g_cand[base + 1] = (fflip(tv1[slot]) & 0xFFFFE000u) | (uint32_t)ti1[slot];
    }
}

// ---------------------------------------------------------------------------
// Kernel 3: warp-per-token merge + exact rescore + gather + MSE partial.
//           Last block also reduces the loss and writes the output tail.
// ---------------------------------------------------------------------------
__global__ __launch_bounds__(256)
void vq_select(const float* __restrict__ x, const float* __restrict__ cb,
               float* __restrict__ out, int nd, int out_size) {
    const int lane = threadIdx.x & 31;
    const int wip = threadIdx.x >> 5;                 // warp in block (0..7)
    const int token = blockIdx.x * 8 + wip;

    const uint32_t* cd = g_cand + (size_t)token * 128;
    uint32_t c[4];
    uint32_t m = 0xFFFFFFFFu;
#pragma unroll
    for (int j = 0; j < 4; j++) { c[j] = cd[lane * 4 + j]; m = min(m, c[j]); }
#pragma unroll
    for (int o = 16; o > 0; o >>= 1)
        m = min(m, __shfl_xor_sync(0xFFFFFFFFu, m, o));
    float thresh = funflip(m & 0xFFFFE000u) + MARGIN;

    const float4* xr = reinterpret_cast<const float4*>(x + (size_t)token * DDIM);
    unsigned long long best = ~0ull;
#pragma unroll
    for (int j = 0; j < 4; j++) {
        if (funflip(c[j] & 0xFFFFE000u) <= thresh) {
            int idx = (int)(c[j] & 0x1FFFu);
            const float4* cr = reinterpret_cast<const float4*>(cb + (size_t)idx * DDIM);
            float dot = 0.f;
#pragma unroll 16
            for (int k = 0; k < DDIM / 4; k++) {
                float4 a = __ldg(&xr[k]);
                float4 b = __ldg(&cr[k]);
                dot += a.x * b.x + a.y * b.y + a.z * b.z + a.w * b.w;
            }
            float es = fmaf(-2.f, dot, __ldg(&g_cnorm[idx]));
            unsigned long long p =
                ((unsigned long long)fflip(es) << 32) | (unsigned)idx;
            best = min(best, p);
        }
    }
#pragma unroll
    for (int o = 16; o > 0; o >>= 1)
        best = min(best, __shfl_xor_sync(0xFFFFFFFFu, best, o));
    int bi = (int)(best & 0x1FFFu);

    // ---- gather winning row + MSE (2 float4 per lane) ----
    const float4* cw = reinterpret_cast<const float4*>(cb + (size_t)bi * DDIM);
    float4* or4 = reinterpret_cast<float4*>(out + (size_t)token * DDIM);
    float mse = 0.f;
#pragma unroll
    for (int j = 0; j < 2; j++) {
        int k = lane * 2 + j;
        float4 cv = __ldg(&cw[k]);
        float4 a = __ldg(&xr[k]);
        or4[k] = cv;
        float dx = cv.x - a.x, dy = cv.y - a.y, dz = cv.z - a.z, dw = cv.w - a.w;
        mse += dx * dx + dy * dy + dz * dz + dw * dw;
    }
#pragma unroll
    for (int o = 16; o > 0; o >>= 1)
        mse += __shfl_xor_sync(0xFFFFFFFFu, mse, o);

    __shared__ float red[8];
    __shared__ int lastflag;
    if (lane == 0) red[wip] = mse;
    __syncthreads();
    if (threadIdx.x == 0) {
        float s = 0.f;
#pragma unroll
        for (int w = 0; w < 8; w++) s += red[w];
        g_partial[blockIdx.x] = s;
        __threadfence();
        lastflag = (atomicAdd(&g_done, 1) == gridDim.x - 1) ? 1 : 0;
    }
    __syncthreads();
    if (!lastflag) return;
    __threadfence();

    // ---- fused finish: deterministic loss reduce + tail write ----
    __shared__ float red2[256];
    float s = 0.f;
    for (int i = threadIdx.x; i < (int)gridDim.x; i += 256) s += g_partial[i];
    red2[threadIdx.x] = s;
    __syncthreads();
    for (int off = 128; off > 0; off >>= 1) {
        if (threadIdx.x < off) red2[threadIdx.x] += red2[threadIdx.x + off];
        __syncthreads();
    }
    float loss = 0.25f * red2[0] / (float)nd;
    for (int i = nd + threadIdx.x; i < out_size; i += 256) out[i] = loss;
}

// ---------------------------------------------------------------------------
extern "C" void kernel_launch(void* const* d_in, const int* in_sizes, int n_in,
                              void* d_out, int out_size) {
    const float* x  = (const float*)d_in[0];
    const float* cb = (const float*)d_in[1];
    float* out = (float*)d_out;

    const int N = in_sizes[0] / DDIM;   // 32768 tokens
    const int K = in_sizes[1] / DDIM;   // 8192 codes
    const int nd = N * DDIM;
    const int sel_blocks = N / 8;       // 4096

    cudaFuncSetAttribute(vq_gemm, cudaFuncAttributeMaxDynamicSharedMemorySize,
                         SMEM_TOTAL);

    vq_prep<<<(K + 7) / 8, 256>>>(cb, K);
    vq_gemm<<<(N / TILE_M) * NPART, 256, SMEM_TOTAL>>>(x);
    vq_select<<<sel_blocks, 256>>>(x, cb, out, nd, out_size);
}

// round 14
// speedup vs baseline: 1.8065x; 1.8065x over previous
#include <cuda_runtime.h>
#include <cuda_fp16.h>
#include <math_constants.h>
#include <cstdint>

// =============================================================================
// VQ forward, fp16 mma.sync f32-acc (compute_103-safe PTX), split-K(codebook):
//   1024 CTAs: (token tile 128) x (code slice 2048). Each CTA emits 32 packed
//   (approx score | idx) candidates per token. vq_select: warp-per-token merge
//   -> exact fp32 rescore in margin -> gather + MSE. vq_finish: loss + tail.
//   Mainloop: 2-stage cp.async ring with ONE __syncthreads per K-slice.
// =============================================================================

#define DDIM 256
#define TILE_M 128          // tokens per CTA
#define TILE_N 128          // codes per n-chunk
#define NPART 4             // codebook split factor
#define KSLICE 2048         // codes per CTA
#define MAX_N 65536
#define MAX_K 8192
#define SEL_BLOCKS 4096
#define MARGIN 1.0f

#define B_OFF     65536     // A tile: 128 rows x 512B = 64KB
#define B_STAGE   16384     // 128 codes x 64 halves x 2B
#define SMEM_TOTAL (B_OFF + 2 * B_STAGE)    // 98304 B -> 2 CTAs/SM

__device__ float    g_cnorm[MAX_K];
__device__ float    g_partial[SEL_BLOCKS];
__device__ __half   g_cb_h[MAX_K * DDIM];
__device__ uint32_t g_cand[MAX_N * 128];    // 32 packed cands x NPART per token

// ------------------------------------------------------------------ helpers
__device__ __forceinline__ uint32_t smem_u32(const void* p) {
    uint32_t a;
    asm("{ .reg .u64 t; cvta.to.shared.u64 t, %1; cvt.u32.u64 %0, t; }"
        : "=r"(a) : "l"(p));
    return a;
}
__device__ __forceinline__ void cp_async16(uint32_t dst, const void* src) {
    asm volatile("cp.async.cg.shared.global [%0], [%1], 16;"
                 :: "r"(dst), "l"(src) : "memory");
}
#define CP_COMMIT() asm volatile("cp.async.commit_group;" ::: "memory")
#define CP_WAIT0()  asm volatile("cp.async.wait_group 0;" ::: "memory")

__device__ __forceinline__ void ldsm4(uint32_t& r0, uint32_t& r1, uint32_t& r2,
                                      uint32_t& r3, uint32_t addr) {
    asm volatile("ldmatrix.sync.aligned.m8n8.x4.shared.b16 {%0,%1,%2,%3}, [%4];"
                 : "=r"(r0), "=r"(r1), "=r"(r2), "=r"(r3) : "r"(addr));
}
__device__ __forceinline__ void mma16816(float* d, const uint32_t* a,
                                         uint32_t b0, uint32_t b1) {
    asm volatile(
        "mma.sync.aligned.m16n8k16.row.col.f32.f16.f16.f32 "
        "{%0,%1,%2,%3}, {%4,%5,%6,%7}, {%8,%9}, {%0,%1,%2,%3};"
        : "+f"(d[0]), "+f"(d[1]), "+f"(d[2]), "+f"(d[3])
        : "r"(a[0]), "r"(a[1]), "r"(a[2]), "r"(a[3]), "r"(b0), "r"(b1));
}
__device__ __forceinline__ uint32_t pack2(unsigned short a, unsigned short b) {
    return (uint32_t)a | ((uint32_t)b << 16);
}
// monotone float<->uint order flip
__device__ __forceinline__ uint32_t fflip(float s) {
    uint32_t u = __float_as_uint(s);
    return u ^ ((uint32_t)((int32_t)u >> 31) | 0x80000000u);
}
__device__ __forceinline__ float funflip(uint32_t u) {
    uint32_t m = (u & 0x80000000u) ? 0x80000000u : 0xFFFFFFFFu;
    return __uint_as_float(u ^ m);
}

// ---------------------------------------------------------------------------
// Kernel 1: fused codebook norms + fp32->fp16 convert. One warp per code row.
// ---------------------------------------------------------------------------
__global__ __launch_bounds__(256)
void vq_prep(const float* __restrict__ cb, int K) {
    int row = blockIdx.x * 8 + (threadIdx.x >> 5);
    int lane = threadIdx.x & 31;
    if (row >= K) return;
    const float4* src = reinterpret_cast<const float4*>(cb + (size_t)row * DDIM);
    float4 v0 = src[lane * 2], v1 = src[lane * 2 + 1];
    float f[8] = {v0.x, v0.y, v0.z, v0.w, v1.x, v1.y, v1.z, v1.w};
    float s = 0.f;
    unsigned short h[8];
#pragma unroll
    for (int c = 0; c < 8; c++) {
        s += f[c] * f[c];
        h[c] = __half_as_ushort(__float2half_rn(f[c]));
    }
#pragma unroll
    for (int o = 16; o > 0; o >>= 1) s += __shfl_down_sync(0xFFFFFFFFu, s, o);
    if (lane == 0) g_cnorm[row] = s;
    reinterpret_cast<uint4*>(g_cb_h + (size_t)row * DDIM)[lane] =
        make_uint4(pack2(h[0], h[1]), pack2(h[2], h[3]),
                   pack2(h[4], h[5]), pack2(h[6], h[7]));
}

// ---------------------------------------------------------------------------
// Kernel 2: fp16 GEMM (128 tokens x 2048 codes) + per-thread top-2 ->
//           packed candidates to global. blockIdx: tile = bx>>2, part = bx&3.
// ---------------------------------------------------------------------------
__global__ __launch_bounds__(256, 2)
void vq_gemm(const float* __restrict__ x) {
    extern __shared__ __align__(1024) char smem[];
    const uint32_t sb = smem_u32(smem);
    const int tid = threadIdx.x;
    const int lane = tid & 31;
    const int warp = tid >> 5;
    const int warp_m = warp >> 2;          // 0..1
    const int warp_n = warp & 3;           // 0..3
    const int part = blockIdx.x & 3;
    const int m0 = (blockIdx.x >> 2) * TILE_M;
    const int n_part0 = part * KSLICE;
    const int G = (KSLICE / TILE_N) * 4;   // 64 B-slices

    // ---- A: load x rows, convert to fp16, swizzled smem (64KB) ----
    for (int g = tid; g < TILE_M * 32; g += 256) {       // 16B granules
        int r = g >> 5, gk = g & 31;
        const float4* src =
            reinterpret_cast<const float4*>(x + (size_t)(m0 + r) * DDIM + gk * 8);
        float4 v0 = src[0], v1 = src[1];
        float f[8] = {v0.x, v0.y, v0.z, v0.w, v1.x, v1.y, v1.z, v1.w};
        unsigned short hs[8];
#pragma unroll
        for (int c = 0; c < 8; c++) hs[c] = __half_as_ushort(__float2half_rn(f[c]));
        uint32_t off = r * 512 + (gk >> 3) * 128 + ((((gk ^ r) & 7)) << 4);
        *reinterpret_cast<uint4*>(smem + off) =
            make_uint4(pack2(hs[0], hs[1]), pack2(hs[2], hs[3]),
                       pack2(hs[4], hs[5]), pack2(hs[6], hs[7]));
    }

    // ---- per-lane ldmatrix address bases ----
    const int a_row = warp_m * 64 + (lane & 15);
    const int a_r7 = a_row & 7;
    uint32_t a_base[4];
#pragma unroll
    for (int mf = 0; mf < 4; mf++) a_base[mf] = sb + (a_row + mf * 16) * 512;
    const int b_nlo = (lane & 7) + ((lane >> 4) << 3);
    const int b_gbit = (lane >> 3) & 1;
    uint32_t b_rowoff[2];
#pragma unroll
    for (int p = 0; p < 2; p++)
        b_rowoff[p] = (warp_n * 32 + p * 16 + b_nlo) * 128;

    float acc[4][4][4];
#pragma unroll
    for (int a1 = 0; a1 < 4; a1++)
#pragma unroll
        for (int a2 = 0; a2 < 4; a2++)
#pragma unroll
            for (int a3 = 0; a3 < 4; a3++) acc[a1][a2][a3] = 0.f;

    float tv0[8], tv1[8];
    int   ti0[8], ti1[8];
#pragma unroll
    for (int s = 0; s < 8; s++) {
        tv0[s] = tv1[s] = CUDART_INF_F;
        ti0[s] = ti1[s] = 0;
    }

    // ---- B slice producer (all 256 threads, 4 x 16B each) ----
    auto issueB = [&](int g) {
        int nc = g >> 2, kc = g & 3;
        const __half* gb =
            g_cb_h + (size_t)(n_part0 + nc * TILE_N) * DDIM + kc * 64;
        uint32_t bbuf = sb + B_OFF + (g & 1) * B_STAGE;
#pragma unroll
        for (int j = 0; j < 4; j++) {
            int lin = tid + j * 256;
            int n = lin >> 3, gk = lin & 7;
            cp_async16(bbuf + n * 128 + (((gk ^ n) & 7) << 4),
                       gb + (size_t)n * DDIM + gk * 8);
        }
        CP_COMMIT();
    };

    issueB(0);

    for (int g = 0; g < G; g++) {
        // Single barrier per slice: wait makes stage g visible to this thread;
        // the sync then (a) publishes stage g to all threads and (b) proves
        // every warp finished compute(g-1), so buf[(g+1)&1] is safe to refill.
        CP_WAIT0();
        __syncthreads();
        if (g + 1 < G) issueB(g + 1);

        const uint32_t bbuf = sb + B_OFF + (g & 1) * B_STAGE;
        const int kc = g & 3;
#pragma unroll
        for (int s = 0; s < 4; s++) {        // k16 steps within slice
            uint32_t br[8];
#pragma unroll
            for (int p = 0; p < 2; p++) {
                int gk = s * 2 + b_gbit;
                uint32_t addr = bbuf + b_rowoff[p] + (((gk ^ b_nlo) & 7) << 4);
                ldsm4(br[p * 4 + 0], br[p * 4 + 1], br[p * 4 + 2], br[p * 4 + 3], addr);
            }
            int kabs = kc * 4 + s;
            int ga = kabs * 2 + (lane >> 4);
            uint32_t aoff = (ga >> 3) * 128 + ((((ga & 7) ^ a_r7)) << 4);
#pragma unroll
            for (int mf = 0; mf < 4; mf++) {
                uint32_t ar[4];
                ldsm4(ar[0], ar[1], ar[2], ar[3], a_base[mf] + aoff);
#pragma unroll
                for (int nf = 0; nf < 4; nf++)
                    mma16816(acc[mf][nf], ar, br[(nf >> 1) * 4 + (nf & 1) * 2],
                             br[(nf >> 1) * 4 + (nf & 1) * 2 + 1]);
            }
        }

        if ((g & 3) == 3) {
            // ---- fold chunk scores into per-row top-2 ----
            int n_base = n_part0 + (g >> 2) * TILE_N + warp_n * 32 + (lane & 3) * 2;
#pragma unroll
            for (int nf = 0; nf < 4; nf++) {
                int ncol = n_base + nf * 8;
                float cn0 = __ldg(&g_cnorm[ncol]);
                float cn1 = __ldg(&g_cnorm[ncol + 1]);
#pragma unroll
                for (int mf = 0; mf < 4; mf++) {
#pragma unroll
                    for (int h = 0; h < 2; h++) {
                        int slot = mf * 2 + h;
                        float s0 = fmaf(-2.f, acc[mf][nf][h * 2 + 0], cn0);
                        float s1 = fmaf(-2.f, acc[mf][nf][h * 2 + 1], cn1);
#pragma unroll
                        for (int q = 0; q < 2; q++) {
                            float sv = q ? s1 : s0;
                            int   si = ncol + q;
                            if (sv < tv1[slot]) {
                                if (sv < tv0[slot]) {
                                    tv1[slot] = tv0[slot]; ti1[slot] = ti0[slot];
                                    tv0[slot] = sv;        ti0[slot] = si;
                                } else { tv1[slot] = sv; ti1[slot] = si; }
                            }
                        }
                        acc[mf][nf][h * 2 + 0] = 0.f;
                        acc[mf][nf][h * 2 + 1] = 0.f;
                    }
                }
            }
        }
    }

    // ---- write packed candidates straight to global (no tail compute) ----
    const int t16 = warp_n * 4 + (lane & 3);
#pragma unroll
    for (int slot = 0; slot < 8; slot++) {
        int row = warp_m * 64 + (slot >> 1) * 16 + (lane >> 2) + (slot & 1) * 8;
        size_t base = (size_t)(m0 + row) * 128 + part * 32 + t16 * 2;
        g_cand[base + 0] = (fflip(tv0[slot]) & 0xFFFFE000u) | (uint32_t)ti0[slot];
        g_cand[base + 1] = (fflip(tv1[slot]) & 0xFFFFE000u) | (uint32_t)ti1[slot];
    }
}

// ---------------------------------------------------------------------------
// Kernel 3: warp-per-token merge + exact rescore + gather + MSE partial.
// ---------------------------------------------------------------------------
__global__ __launch_bounds__(256)
void vq_select(const float* __restrict__ x, const float* __restrict__ cb,
               float* __restrict__ out) {
    const int lane = threadIdx.x & 31;
    const int wip = threadIdx.x >> 5;                 // warp in block (0..7)
    const int token = blockIdx.x * 8 + wip;

    const uint32_t* cd = g_cand + (size_t)token * 128;
    uint32_t c[4];
    uint32_t m = 0xFFFFFFFFu;
#pragma unroll
    for (int j = 0; j < 4; j++) { c[j] = cd[lane * 4 + j]; m = min(m, c[j]); }
#pragma unroll
    for (int o = 16; o > 0; o >>= 1)
        m = min(m, __shfl_xor_sync(0xFFFFFFFFu, m, o));
    float thresh = funflip(m & 0xFFFFE000u) + MARGIN;

    const float4* xr = reinterpret_cast<const float4*>(x + (size_t)token * DDIM);
    unsigned long long best = ~0ull;
#pragma unroll
    for (int j = 0; j < 4; j++) {
        if (funflip(c[j] & 0xFFFFE000u) <= thresh) {
            int idx = (int)(c[j] & 0x1FFFu);
            const float4* cr = reinterpret_cast<const float4*>(cb + (size_t)idx * DDIM);
            float dot = 0.f;
#pragma unroll 16
            for (int k = 0; k < DDIM / 4; k++) {
                float4 a = __ldg(&xr[k]);
                float4 b = __ldg(&cr[k]);
                dot += a.x * b.x + a.y * b.y + a.z * b.z + a.w * b.w;
            }
            float es = fmaf(-2.f, dot, __ldg(&g_cnorm[idx]));
            unsigned long long p =
                ((unsigned long long)fflip(es) << 32) | (unsigned)idx;
            best = min(best, p);
        }
    }
#pragma unroll
    for (int o = 16; o > 0; o >>= 1)
        best = min(best, __shfl_xor_sync(0xFFFFFFFFu, best, o));
    int bi = (int)(best & 0x1FFFu);

    // ---- gather winning row + MSE (2 float4 per lane) ----
    const float4* cw = reinterpret_cast<const float4*>(cb + (size_t)bi * DDIM);
    float4* or4 = reinterpret_cast<float4*>(out + (size_t)token * DDIM);
    float mse = 0.f;
#pragma unroll
    for (int j = 0; j < 2; j++) {
        int k = lane * 2 + j;
        float4 cv = __ldg(&cw[k]);
        float4 a = __ldg(&xr[k]);
        or4[k] = cv;
        float dx = cv.x - a.x, dy = cv.y - a.y, dz = cv.z - a.z, dw = cv.w - a.w;
        mse += dx * dx + dy * dy + dz * dz + dw * dw;
    }
#pragma unroll
    for (int o = 16; o > 0; o >>= 1)
        mse += __shfl_xor_sync(0xFFFFFFFFu, mse, o);

    __shared__ float red[8];
    if (lane == 0) red[wip] = mse;
    __syncthreads();
    if (threadIdx.x == 0) {
        float s = 0.f;
#pragma unroll
        for (int w = 0; w < 8; w++) s += red[w];
        g_partial[blockIdx.x] = s;
    }
}

// ---------------------------------------------------------------------------
// Kernel 4: final loss reduction (parallel, deterministic), write tail
// ---------------------------------------------------------------------------
__global__ void vq_finish(float* __restrict__ out, int nd, int out_size, int nblocks) {
    __shared__ float red[256];
    float s = 0.f;
    for (int i = threadIdx.x; i < nblocks; i += 256) s += g_partial[i];
    red[threadIdx.x] = s;
    __syncthreads();
    for (int off = 128; off > 0; off >>= 1) {
        if (threadIdx.x < off) red[threadIdx.x] += red[threadIdx.x + off];
        __syncthreads();
    }
    float loss = 0.25f * red[0] / (float)nd;
    for (int i = nd + threadIdx.x; i < out_size; i += 256) out[i] = loss;
}

// ---------------------------------------------------------------------------
extern "C" void kernel_launch(void* const* d_in, const int* in_sizes, int n_in,
                              void* d_out, int out_size) {
    const float* x  = (const float*)d_in[0];
    const float* cb = (const float*)d_in[1];
    float* out = (float*)d_out;

    const int N = in_sizes[0] / DDIM;   // 32768 tokens
    const int K = in_sizes[1] / DDIM;   // 8192 codes
    const int nd = N * DDIM;
    const int sel_blocks = N / 8;       // 4096

    cudaFuncSetAttribute(vq_gemm, cudaFuncAttributeMaxDynamicSharedMemorySize,
                         SMEM_TOTAL);

    vq_prep<<<(K + 7) / 8, 256>>>(cb, K);
    vq_gemm<<<(N / TILE_M) * NPART, 256, SMEM_TOTAL>>>(x);
    vq_select<<<sel_blocks, 256>>>(x, cb, out);
    vq_finish<<<1, 256>>>(out, nd, out_size, sel_blocks);
}